// round 2
// baseline (speedup 1.0000x reference)
#include <cuda_runtime.h>

// Problem constants: S=7, B=2, C=20, E=30, BATCH=16384
// cells = 16384*7*7 = 802816 = 6272 * 128 (exact), each cell: 30 floats per tensor.

#define TPB 128
#define FLOATS_PER_BLOCK (TPB * 30)        // 3840
#define VEC4_PER_BLOCK   (FLOATS_PER_BLOCK / 4)  // 960

__global__ void zero_out_kernel(float* out) {
    if (threadIdx.x < 5) out[threadIdx.x] = 0.0f;
}

__global__ void __launch_bounds__(TPB) yolo_loss_kernel(
    const float* __restrict__ pred,
    const float* __restrict__ tgt,
    float* __restrict__ out)
{
    __shared__ float sp[FLOATS_PER_BLOCK];
    __shared__ float st[FLOATS_PER_BLOCK];

    const int tid = threadIdx.x;
    const size_t blockBase = (size_t)blockIdx.x * FLOATS_PER_BLOCK;

    // ---- coalesced staging: consecutive lanes -> consecutive float4 ----
    const float4* gp = reinterpret_cast<const float4*>(pred + blockBase);
    const float4* gt = reinterpret_cast<const float4*>(tgt  + blockBase);
    float4* s4p = reinterpret_cast<float4*>(sp);
    float4* s4t = reinterpret_cast<float4*>(st);

    #pragma unroll
    for (int i = tid; i < VEC4_PER_BLOCK; i += TPB) {
        s4p[i] = gp[i];
        s4t[i] = gt[i];
    }
    __syncthreads();

    // ---- per-cell compute from smem (LDS.64, conflict-free at stride 120B) ----
    const float* p = &sp[tid * 30];
    const float* t = &st[tid * 30];

    float m  = (t[4] > 0.0f) ? 1.0f : 0.0f;  // conf is exactly 0.0 or 1.0
    float nm = 1.0f - m;

    // IoU of each pred box vs target box 0
    float tx0 = t[0], ty0 = t[1], tx1 = t[2], ty1 = t[3];
    float a2 = (tx1 - tx0) * (ty1 - ty0);
    float iou[2];
    #pragma unroll
    for (int b = 0; b < 2; b++) {
        float p0 = p[5*b + 0], p1 = p[5*b + 1], p2v = p[5*b + 2], p3 = p[5*b + 3];
        float ltx = fmaxf(p0, tx0), lty = fmaxf(p1, ty0);
        float rbx = fminf(p2v, tx1), rby = fminf(p3, ty1);
        float w = fmaxf(rbx - ltx, 0.0f);
        float h = fmaxf(rby - lty, 0.0f);
        float inter = w * h;
        float a1 = (p2v - p0) * (p3 - p1);
        iou[b] = inter / (a1 + a2 - inter);
    }
    // jnp.argmax: first index of max -> strict greater-than for box 1
    int idx = (iou[1] > iou[0]) ? 1 : 0;
    float maxiou = fmaxf(iou[0], iou[1]);

    const float* pb = &p[5 * idx];
    const float* tb = &t[5 * idx];

    float dx = pb[0] - tb[0], dy = pb[1] - tb[1];
    float lxy = m * (dx * dx + dy * dy);

    float dw = sqrtf(pb[2]) - sqrtf(tb[2]);
    float dh = sqrtf(pb[3]) - sqrtf(tb[3]);
    float lwh = m * (dw * dw + dh * dh);

    float dobj = pb[4] - maxiou;
    float lobj = m * dobj * dobj;

    float d4 = p[4] - t[4], d9 = p[9] - t[9];
    float lnoobj = nm * (d4 * d4 + d9 * d9);

    float cs = 0.0f;
    #pragma unroll
    for (int c = 10; c < 30; c++) {
        float d = p[c] - t[c];
        cs = fmaf(d, d, cs);
    }
    float lcls = m * cs;

    // ---- block reduction: warp shuffle then shared ----
    #pragma unroll
    for (int off = 16; off > 0; off >>= 1) {
        lxy    += __shfl_down_sync(0xffffffff, lxy,    off);
        lwh    += __shfl_down_sync(0xffffffff, lwh,    off);
        lobj   += __shfl_down_sync(0xffffffff, lobj,   off);
        lnoobj += __shfl_down_sync(0xffffffff, lnoobj, off);
        lcls   += __shfl_down_sync(0xffffffff, lcls,   off);
    }

    __shared__ float red[5][4];
    int wid  = tid >> 5;
    int lane = tid & 31;
    if (lane == 0) {
        red[0][wid] = lxy;
        red[1][wid] = lwh;
        red[2][wid] = lobj;
        red[3][wid] = lnoobj;
        red[4][wid] = lcls;
    }
    __syncthreads();

    if (tid < 5) {
        float s = red[tid][0] + red[tid][1] + red[tid][2] + red[tid][3];
        atomicAdd(&out[tid], s);
    }
}

extern "C" void kernel_launch(void* const* d_in, const int* in_sizes, int n_in,
                              void* d_out, int out_size) {
    const float* pred = (const float*)d_in[0];
    const float* tgt  = (const float*)d_in[1];
    float* out = (float*)d_out;

    int ncells = in_sizes[0] / 30;       // 802816
    int blocks = ncells / TPB;           // 6272 (exact)

    zero_out_kernel<<<1, 32>>>(out);
    yolo_loss_kernel<<<blocks, TPB>>>(pred, tgt, out);
}

// round 3
// speedup vs baseline: 1.0237x; 1.0237x over previous
#include <cuda_runtime.h>
#include <cstdint>
#include <cstddef>

// S=7, B=2, C=20, E=30, BATCH=16384. cells = 802816 = 6272 tiles of 128.
#define TPB 128
#define CELLS_PER_TILE 128
#define FLOATS_PER_ARRAY_TILE (CELLS_PER_TILE * 30)        // 3840 floats
#define BYTES_PER_ARRAY_TILE  (FLOATS_PER_ARRAY_TILE * 4)  // 15360 B
#define VEC16_PER_ARRAY       (BYTES_PER_ARRAY_TILE / 16)  // 960
#define STAGE_FLOATS (2 * FLOATS_PER_ARRAY_TILE)           // pred + tgt = 7680 floats
#define STAGE_BYTES  (STAGE_FLOATS * 4)                    // 30720 B
#define NSTAGE 2
#define SMEM_BYTES (NSTAGE * STAGE_BYTES)                  // 61440 B

__device__ __forceinline__ void cp_async16(uint32_t s_dst, const void* g_src) {
    asm volatile("cp.async.cg.shared.global [%0], [%1], 16;\n" :: "r"(s_dst), "l"(g_src));
}
__device__ __forceinline__ void cp_commit() {
    asm volatile("cp.async.commit_group;\n" ::: "memory");
}
template <int N>
__device__ __forceinline__ void cp_wait() {
    asm volatile("cp.async.wait_group %0;\n" :: "n"(N) : "memory");
}

__global__ void zero_out_kernel(float* out) {
    if (threadIdx.x < 5) out[threadIdx.x] = 0.0f;
}

__global__ void __launch_bounds__(TPB, 3) yolo_loss_kernel(
    const float* __restrict__ pred,
    const float* __restrict__ tgt,
    float* __restrict__ out,
    int ntiles)
{
    extern __shared__ float smem[];
    uint32_t sbase;
    asm("{ .reg .u64 t; cvta.to.shared.u64 t, %1; cvt.u32.u64 %0, t; }"
        : "=r"(sbase) : "l"(smem));

    const int tid = threadIdx.x;
    const int G = gridDim.x;

    float accXY = 0.f, accWH = 0.f, accOBJ = 0.f, accNO = 0.f, accCLS = 0.f;

    // ---- prologue: prefetch first tile into stage 0 ----
    int k = blockIdx.x;
    {
        const char* psrc = (const char*)pred + (size_t)k * BYTES_PER_ARRAY_TILE;
        const char* tsrc = (const char*)tgt  + (size_t)k * BYTES_PER_ARRAY_TILE;
        #pragma unroll
        for (int j = 0; j < 15; j++) {
            int i = tid + j * TPB;                 // 0..1919
            const char* src = (i < VEC16_PER_ARRAY)
                ? psrc + (size_t)i * 16
                : tsrc + (size_t)(i - VEC16_PER_ARRAY) * 16;
            cp_async16(sbase + (uint32_t)i * 16, src);
        }
    }
    cp_commit();

    int s = 0;
    for (; k < ntiles; k += G, s ^= 1) {
        // ---- prefetch next tile into the other stage (issued before compute) ----
        int knext = k + G;
        if (knext < ntiles) {
            uint32_t dbase = sbase + (uint32_t)(s ^ 1) * STAGE_BYTES;
            const char* psrc = (const char*)pred + (size_t)knext * BYTES_PER_ARRAY_TILE;
            const char* tsrc = (const char*)tgt  + (size_t)knext * BYTES_PER_ARRAY_TILE;
            #pragma unroll
            for (int j = 0; j < 15; j++) {
                int i = tid + j * TPB;
                const char* src = (i < VEC16_PER_ARRAY)
                    ? psrc + (size_t)i * 16
                    : tsrc + (size_t)(i - VEC16_PER_ARRAY) * 16;
                cp_async16(dbase + (uint32_t)i * 16, src);
            }
        }
        cp_commit();          // group for tile knext (possibly empty)
        cp_wait<1>();         // oldest group (tile k) complete
        __syncthreads();      // all threads' copies visible block-wide

        // ---- compute current tile from smem ----
        const float* p = smem + s * STAGE_FLOATS + tid * 30;
        const float* t = smem + s * STAGE_FLOATS + FLOATS_PER_ARRAY_TILE + tid * 30;

        float m  = (t[4] > 0.0f) ? 1.0f : 0.0f;   // conf is exactly 0.0 or 1.0
        float nm = 1.0f - m;

        float tx0 = t[0], ty0 = t[1], tx1 = t[2], ty1 = t[3];
        float a2 = (tx1 - tx0) * (ty1 - ty0);
        float iou[2];
        #pragma unroll
        for (int b = 0; b < 2; b++) {
            float p0 = p[5*b+0], p1 = p[5*b+1], p2v = p[5*b+2], p3 = p[5*b+3];
            float ltx = fmaxf(p0, tx0), lty = fmaxf(p1, ty0);
            float rbx = fminf(p2v, tx1), rby = fminf(p3, ty1);
            float w = fmaxf(rbx - ltx, 0.0f);
            float h = fmaxf(rby - lty, 0.0f);
            float inter = w * h;
            float a1 = (p2v - p0) * (p3 - p1);
            iou[b] = inter / (a1 + a2 - inter);
        }
        int idx = (iou[1] > iou[0]) ? 1 : 0;       // jnp.argmax: first max wins
        float maxiou = fmaxf(iou[0], iou[1]);

        const float* pb = &p[5 * idx];
        const float* tb = &t[5 * idx];

        float dx = pb[0] - tb[0], dy = pb[1] - tb[1];
        accXY = fmaf(m, dx*dx + dy*dy, accXY);

        float dw = sqrtf(pb[2]) - sqrtf(tb[2]);
        float dh = sqrtf(pb[3]) - sqrtf(tb[3]);
        accWH = fmaf(m, dw*dw + dh*dh, accWH);

        float dobj = pb[4] - maxiou;
        accOBJ = fmaf(m, dobj*dobj, accOBJ);

        float d4 = p[4] - t[4], d9 = p[9] - t[9];
        accNO = fmaf(nm, d4*d4 + d9*d9, accNO);

        float cs = 0.0f;
        #pragma unroll
        for (int c = 10; c < 30; c++) {
            float d = p[c] - t[c];
            cs = fmaf(d, d, cs);
        }
        accCLS = fmaf(m, cs, accCLS);

        __syncthreads();      // everyone done reading stage s before it's refilled
    }

    // ---- final block reduction (once) ----
    #pragma unroll
    for (int off = 16; off > 0; off >>= 1) {
        accXY  += __shfl_down_sync(0xffffffff, accXY,  off);
        accWH  += __shfl_down_sync(0xffffffff, accWH,  off);
        accOBJ += __shfl_down_sync(0xffffffff, accOBJ, off);
        accNO  += __shfl_down_sync(0xffffffff, accNO,  off);
        accCLS += __shfl_down_sync(0xffffffff, accCLS, off);
    }

    __shared__ float red[5][4];
    int wid  = tid >> 5;
    int lane = tid & 31;
    if (lane == 0) {
        red[0][wid] = accXY;
        red[1][wid] = accWH;
        red[2][wid] = accOBJ;
        red[3][wid] = accNO;
        red[4][wid] = accCLS;
    }
    __syncthreads();

    if (tid < 5) {
        float v = red[tid][0] + red[tid][1] + red[tid][2] + red[tid][3];
        atomicAdd(&out[tid], v);
    }
}

extern "C" void kernel_launch(void* const* d_in, const int* in_sizes, int n_in,
                              void* d_out, int out_size) {
    const float* pred = (const float*)d_in[0];
    const float* tgt  = (const float*)d_in[1];
    float* out = (float*)d_out;

    int ncells = in_sizes[0] / 30;            // 802816
    int ntiles = ncells / CELLS_PER_TILE;     // 6272 (exact)

    int dev = 0, nsm = 148;
    cudaGetDevice(&dev);
    cudaDeviceGetAttribute(&nsm, cudaDevAttrMultiProcessorCount, dev);

    cudaFuncSetAttribute(yolo_loss_kernel,
                         cudaFuncAttributeMaxDynamicSharedMemorySize, SMEM_BYTES);

    int grid = 3 * nsm;                       // 3 resident blocks per SM
    if (grid > ntiles) grid = ntiles;

    zero_out_kernel<<<1, 32>>>(out);
    yolo_loss_kernel<<<grid, TPB, SMEM_BYTES>>>(pred, tgt, out, ntiles);
}